// round 2
// baseline (speedup 1.0000x reference)
#include <cuda_runtime.h>
#include <cuda_bf16.h>
#include <math.h>
#include <math_constants.h>

// Problem constants
#define BQ  8
#define HQ  8
#define BH  64          // B*H
#define LQ  2048
#define DQ  64
#define NSEL 40         // num selected queries == num sampled keys
#define SCALE 0.125f    // 64^-0.5
#define NEG_INF (-CUDART_INF_F)

// ---------------- scratch (device globals; no allocation allowed) ----------
__device__ float g_measure[BH * LQ];
__device__ int   g_topidx[BH * NSEL];
__device__ float g_rowMaxPart[BH * 8 * NSEL];
__device__ float g_rowSumPart[BH * 8 * NSEL];
__device__ float g_rowMax[BH * NSEL];
__device__ float g_rowInv[BH * NSEL];
__device__ float g_outSel[BH * NSEL * DQ];
__device__ float g_chunkSum[BH * 16 * DQ];

// ============================================================================
// K1: measure[bh][i] = max_j (q_i . k_{ridx[i,j]}) - (sum_j ...) / L
// Chunked-smem gather. Block = (bh, 256 queries), 512 threads.
// Dynamic smem: qs[256*64] (64KB) + ks[256*64] (64KB) + per-warp hit lists.
// 8 chunks of 256 K-rows. Per (query,chunk): ballot-classify the 40 indices,
// compact hit rows to smem list, process 4 hits at a time (4 independent
// butterfly-reduction chains for latency hiding).
// ============================================================================
#define MQ   256                    // queries per block
#define MCH  256                    // K rows per chunk
#define NCH  (LQ / MCH)             // 8 chunks
#define WL_STRIDE 48                // per-warp list capacity (>= NSEL, 16B aligned)
#define SMEM_MEAS ((2 * MQ * DQ) * 4 + 16 * WL_STRIDE * 4)

__global__ __launch_bounds__(512) void k_measure(const float* __restrict__ q,
                                                 const float* __restrict__ k,
                                                 const int* __restrict__ ridx) {
    extern __shared__ float dyn[];
    float* qs = dyn;                       // [MQ][64]
    float* ks = dyn + MQ * DQ;             // [MCH][64]
    int*   wlist = (int*)(dyn + 2 * MQ * DQ);

    const unsigned F = 0xffffffffu;
    int bh = blockIdx.x >> 3;
    int q0 = (blockIdx.x & 7) << 8;
    int tid = threadIdx.x;
    int warp = tid >> 5, lane = tid & 31;
    int wbase = warp * WL_STRIDE;

    // init hit lists to 0 (rows must stay < MCH even when reading stale slots)
    for (int e = tid; e < 16 * WL_STRIDE; e += 512) wlist[e] = 0;

    // stage Q slice [q0, q0+256)
    {
        const float4* src = reinterpret_cast<const float4*>(q + ((size_t)bh * LQ + q0) * DQ);
        float4* dst = reinterpret_cast<float4*>(qs);
        for (int e = tid; e < MQ * (DQ / 4); e += 512) dst[e] = src[e];
    }

    const float* kb = k + (size_t)bh * LQ * DQ;

    // lane qq (<16) owns state of local query warp*16+qq
    float m = NEG_INF, s = 0.0f;

    for (int c = 0; c < NCH; c++) {
        __syncthreads();   // previous chunk fully consumed (also covers qs on c=0)
        {
            const float4* src = reinterpret_cast<const float4*>(kb + (size_t)c * MCH * DQ);
            float4* dst = reinterpret_cast<float4*>(ks);
            for (int e = tid; e < MCH * (DQ / 4); e += 512) dst[e] = src[e];
        }
        __syncthreads();

        for (int qq = 0; qq < 16; qq++) {
            int il = (warp << 4) + qq;     // local query
            int i = q0 + il;               // global query
            int ia = ridx[i * NSEL + lane];
            int ib = (lane < 8) ? ridx[i * NSEL + 32 + lane] : -1;
            unsigned ma = __ballot_sync(F, (ia >> 8) == c);
            unsigned mb = __ballot_sync(F, (ib >> 8) == c);
            int nh = __popc(ma) + __popc(mb);
            if (nh == 0) continue;

            unsigned below = (1u << lane) - 1u;
            if (ma & (1u << lane)) wlist[wbase + __popc(ma & below)] = ia & 255;
            if (mb & (1u << lane)) wlist[wbase + __popc(ma) + __popc(mb & below)] = ib & 255;
            __syncwarp();

            float2 qv = reinterpret_cast<const float2*>(qs)[il * 32 + lane];
            const float2* k2 = reinterpret_cast<const float2*>(ks);

            float lm = NEG_INF, ls = 0.0f;
            for (int h = 0; h < nh; h += 4) {
                int4 r4 = *reinterpret_cast<const int4*>(&wlist[wbase + h]);
                bool v1 = (h + 1 < nh), v2 = (h + 2 < nh), v3 = (h + 3 < nh);
                float2 k0 = k2[(r4.x << 5) + lane];
                float2 k1 = k2[(r4.y << 5) + lane];
                float2 kq2 = k2[(r4.z << 5) + lane];
                float2 k3 = k2[(r4.w << 5) + lane];
                float d0 = qv.x * k0.x + qv.y * k0.y;
                float d1 = qv.x * k1.x + qv.y * k1.y;
                float d2 = qv.x * kq2.x + qv.y * kq2.y;
                float d3 = qv.x * k3.x + qv.y * k3.y;
#pragma unroll
                for (int st = 16; st >= 1; st >>= 1) {
                    d0 += __shfl_xor_sync(F, d0, st);
                    d1 += __shfl_xor_sync(F, d1, st);
                    d2 += __shfl_xor_sync(F, d2, st);
                    d3 += __shfl_xor_sync(F, d3, st);
                }
                lm = fmaxf(lm, d0); ls += d0;
                if (v1) { lm = fmaxf(lm, d1); ls += d1; }
                if (v2) { lm = fmaxf(lm, d2); ls += d2; }
                if (v3) { lm = fmaxf(lm, d3); ls += d3; }
            }
            if (lane == qq) { m = fmaxf(m, lm); s += ls; }
        }
    }
    if (lane < 16)
        g_measure[bh * LQ + q0 + (warp << 4) + lane] = m - s * (1.0f / (float)LQ);
}

// ============================================================================
// K2: per (b,h) top-40 of 2048 via 4-pass byte radix select + rank sort.
// Matches jax.lax.top_k: descending value, ties -> lower index first.
// One block (256 thr) per bh.
// ============================================================================
__global__ void k_topk() {
    __shared__ unsigned ukey[LQ];
    __shared__ int hist[256];
    __shared__ int ssum[256];
    __shared__ int wsum[8];
    __shared__ int s_chosen;
    __shared__ int s_target;
    __shared__ int cnt_gt;
    __shared__ unsigned selKey[64];
    __shared__ int selIdx[64];
    __shared__ int tcnt[256];

    int bh = blockIdx.x, t = threadIdx.x, lane = t & 31, w = t >> 5;

    for (int e = t; e < LQ; e += 256) {
        unsigned b = __float_as_uint(g_measure[bh * LQ + e]);
        ukey[e] = (b & 0x80000000u) ? ~b : (b | 0x80000000u);
    }
    if (t == 0) { s_target = NSEL; cnt_gt = 0; }
    __syncthreads();

    unsigned prefix = 0;
    for (int pass = 3; pass >= 0; pass--) {
        int shift = pass * 8;
        hist[t] = 0;
        __syncthreads();
        unsigned himask = (pass == 3) ? 0u : (0xFFFFFFFFu << (shift + 8));
        for (int e = t; e < LQ; e += 256) {
            unsigned u = ukey[e];
            if ((u & himask) == (prefix & himask))
                atomicAdd(&hist[(u >> shift) & 255], 1);
        }
        __syncthreads();
        // suffix sums S[b] = count of candidate keys with byte >= b
        int r = 255 - t;
        int x = hist[r];
#pragma unroll
        for (int o = 1; o < 32; o <<= 1) {
            int y = __shfl_up_sync(0xffffffffu, x, o);
            if (lane >= o) x += y;
        }
        if (lane == 31) wsum[w] = x;
        __syncthreads();
        if (w == 0 && lane < 8) {
            int y = wsum[lane];
#pragma unroll
            for (int o = 1; o < 8; o <<= 1) {
                int z = __shfl_up_sync(0xffu, y, o);
                if (lane >= o) y += z;
            }
            wsum[lane] = y;
        }
        __syncthreads();
        int S = x + (w > 0 ? wsum[w - 1] : 0);
        ssum[r] = S;
        __syncthreads();
        int target = s_target;
        int Sb = ssum[t];
        int Sb1 = (t == 255) ? 0 : ssum[t + 1];
        if (Sb >= target && Sb1 < target) s_chosen = t;
        __syncthreads();
        int chosen = s_chosen;
        prefix |= ((unsigned)chosen) << shift;
        if (t == 0) s_target = target - ((chosen == 255) ? 0 : ssum[chosen + 1]);
        __syncthreads();
    }
    unsigned T = prefix;
    int need_eq = s_target;
    int count_gt = NSEL - need_eq;

    // collect strictly-greater + count ties per thread (blocked distribution)
    int mytie = 0;
#pragma unroll
    for (int e2 = 0; e2 < 8; e2++) {
        int e = t * 8 + e2;
        unsigned u = ukey[e];
        if (u > T) {
            int p = atomicAdd(&cnt_gt, 1);
            selKey[p] = u; selIdx[p] = e;
        } else if (u == T) mytie++;
    }
    tcnt[t] = mytie;
    __syncthreads();
    // exclusive scan tie counts -> emit lowest-index ties
    {
        int x = tcnt[t];
#pragma unroll
        for (int o = 1; o < 32; o <<= 1) {
            int y = __shfl_up_sync(0xffffffffu, x, o);
            if (lane >= o) x += y;
        }
        if (lane == 31) wsum[w] = x;
        __syncthreads();
        if (w == 0 && lane < 8) {
            int y = wsum[lane];
#pragma unroll
            for (int o = 1; o < 8; o <<= 1) {
                int z = __shfl_up_sync(0xffu, y, o);
                if (lane >= o) y += z;
            }
            wsum[lane] = y;
        }
        __syncthreads();
        int run = x - tcnt[t] + (w > 0 ? wsum[w - 1] : 0);
#pragma unroll
        for (int e2 = 0; e2 < 8; e2++) {
            int e = t * 8 + e2;
            if (ukey[e] == T) {
                if (run < need_eq) { selKey[count_gt + run] = T; selIdx[count_gt + run] = e; }
                run++;
            }
        }
    }
    __syncthreads();
    // rank sort 40: (key desc, idx asc)
    if (t < NSEL) {
        unsigned mk = selKey[t]; int mi = selIdx[t];
        int rank = 0;
        for (int f = 0; f < NSEL; f++) {
            unsigned fk = selKey[f]; int fi = selIdx[f];
            if (fk > mk || (fk == mk && fi < mi)) rank++;
        }
        g_topidx[bh * NSEL + rank] = mi;
    }
}

// ============================================================================
// K3: logits = (q_sel @ k^T)*SCALE with causal mask (j > idx -> -inf),
// written to attn buffer; also per-row partial max / sumexp per 256-key split.
// grid (BH, 8), block 256. Register-tiled 40x128 per subtile.
// ============================================================================
__global__ void k_logits(const float* __restrict__ q,
                         const float* __restrict__ k,
                         float* __restrict__ attn) {
    __shared__ float qs[NSEL * DQ];        // 40x64
    __shared__ float ks[128 * 65];         // padded
    __shared__ int   sidx[NSEL];

    int bh = blockIdx.x, js = blockIdx.y, t = threadIdx.x;
    if (t < NSEL) sidx[t] = g_topidx[bh * NSEL + t];
    __syncthreads();

    for (int e = t; e < NSEL * DQ; e += 256) {
        int s = e >> 6, d = e & 63;
        qs[e] = q[((size_t)bh * LQ + sidx[s]) * DQ + d];
    }

    float* attnBH = attn + (size_t)bh * NSEL * LQ;
    int tx = t & 63, ty = t >> 6;   // tx: key col base, ty: 0..3 row group

    for (int sub = 0; sub < 2; sub++) {
        int j0 = js * 256 + sub * 128;
        __syncthreads();
        for (int e = t; e < 128 * DQ; e += 256) {
            int r = e >> 6, d = e & 63;
            ks[r * 65 + d] = k[((size_t)bh * LQ + j0 + r) * DQ + d];
        }
        __syncthreads();

        float acc[10][2];
#pragma unroll
        for (int r = 0; r < 10; r++) { acc[r][0] = 0.0f; acc[r][1] = 0.0f; }

#pragma unroll 4
        for (int d = 0; d < DQ; d++) {
            float k0 = ks[tx * 65 + d];
            float k1 = ks[(tx + 64) * 65 + d];
#pragma unroll
            for (int r = 0; r < 10; r++) {
                float qv = qs[(ty + 4 * r) * DQ + d];
                acc[r][0] = fmaf(qv, k0, acc[r][0]);
                acc[r][1] = fmaf(qv, k1, acc[r][1]);
            }
        }
#pragma unroll
        for (int r = 0; r < 10; r++) {
            int s = ty + 4 * r;
            int lim = sidx[s];
            int jg0 = j0 + tx;
            int jg1 = j0 + tx + 64;
            attnBH[(size_t)s * LQ + jg0] = (jg0 > lim) ? NEG_INF : acc[r][0] * SCALE;
            attnBH[(size_t)s * LQ + jg1] = (jg1 > lim) ? NEG_INF : acc[r][1] * SCALE;
        }
    }
    __syncthreads();   // make our global logit writes visible block-wide

    // partial softmax stats over this block's 256-key span
    int w = t >> 5, lane = t & 31;
    for (int rr = 0; rr < 5; rr++) {
        int s = w + 8 * rr;
        size_t base = (size_t)s * LQ + js * 256;
        float m = NEG_INF;
#pragma unroll
        for (int u = 0; u < 8; u++) m = fmaxf(m, attnBH[base + lane + 32 * u]);
        m = fmaxf(m, __shfl_xor_sync(0xffffffffu, m, 16));
        m = fmaxf(m, __shfl_xor_sync(0xffffffffu, m, 8));
        m = fmaxf(m, __shfl_xor_sync(0xffffffffu, m, 4));
        m = fmaxf(m, __shfl_xor_sync(0xffffffffu, m, 2));
        m = fmaxf(m, __shfl_xor_sync(0xffffffffu, m, 1));
        float ssum = 0.0f;
        if (m > NEG_INF) {
#pragma unroll
            for (int u = 0; u < 8; u++) ssum += expf(attnBH[base + lane + 32 * u] - m);
        }
        ssum += __shfl_xor_sync(0xffffffffu, ssum, 16);
        ssum += __shfl_xor_sync(0xffffffffu, ssum, 8);
        ssum += __shfl_xor_sync(0xffffffffu, ssum, 4);
        ssum += __shfl_xor_sync(0xffffffffu, ssum, 2);
        ssum += __shfl_xor_sync(0xffffffffu, ssum, 1);
        if (lane == 0) {
            g_rowMaxPart[(bh * 8 + js) * NSEL + s] = m;
            g_rowSumPart[(bh * 8 + js) * NSEL + s] = ssum;
        }
    }
}

// ============================================================================
// K3b: combine partial stats -> final rowMax / 1/rowSum; zero outSel scratch
// ============================================================================
__global__ void k_combine() {
    int bh = blockIdx.x, t = threadIdx.x;
    if (t < NSEL) {
        float fm = NEG_INF;
#pragma unroll
        for (int p = 0; p < 8; p++)
            fm = fmaxf(fm, g_rowMaxPart[(bh * 8 + p) * NSEL + t]);
        float fs = 0.0f;
#pragma unroll
        for (int p = 0; p < 8; p++) {
            float pm = g_rowMaxPart[(bh * 8 + p) * NSEL + t];
            float ps = g_rowSumPart[(bh * 8 + p) * NSEL + t];
            fs += ps * expf(pm - fm);
        }
        g_rowMax[bh * NSEL + t] = fm;
        g_rowInv[bh * NSEL + t] = 1.0f / fs;
    }
    for (int e = t; e < NSEL * DQ; e += 64) g_outSel[bh * NSEL * DQ + e] = 0.0f;
}

// ============================================================================
// cumsum(v, axis=L): 3-pass chunk scan (chunk = 128 rows, 16 chunks)
// ============================================================================
__global__ void k_csumA(const float* __restrict__ v) {       // grid (BH,16), 256 thr
    int bh = blockIdx.x, c = blockIdx.y, t = threadIdx.x;
    int d = t & 63, g = t >> 6;
    const float* base = v + ((size_t)bh * LQ + c * 128) * DQ;
    float s = 0.0f;
#pragma unroll 8
    for (int r = g * 32; r < g * 32 + 32; r++) s += base[(size_t)r * DQ + d];
    __shared__ float red[256];
    red[t] = s;
    __syncthreads();
    if (g == 0)
        g_chunkSum[(bh * 16 + c) * DQ + d] = red[d] + red[64 + d] + red[128 + d] + red[192 + d];
}

__global__ void k_csumB() {                                  // grid BH, 64 thr
    int bh = blockIdx.x, d = threadIdx.x;
    float run = 0.0f;
#pragma unroll
    for (int c = 0; c < 16; c++) {
        float x = g_chunkSum[(bh * 16 + c) * DQ + d];
        g_chunkSum[(bh * 16 + c) * DQ + d] = run;   // exclusive
        run += x;
    }
}

__global__ void k_csumC(const float* __restrict__ v, float* __restrict__ out) { // grid (BH,16), 64 thr
    int bh = blockIdx.x, c = blockIdx.y, d = threadIdx.x;
    const float* base = v + ((size_t)bh * LQ + c * 128) * DQ;
    float* obase = out + ((size_t)bh * LQ + c * 128) * DQ;
    float run = g_chunkSum[(bh * 16 + c) * DQ + d];
#pragma unroll 8
    for (int r = 0; r < 128; r++) {
        run += base[(size_t)r * DQ + d];
        obase[(size_t)r * DQ + d] = run;
    }
}

// ============================================================================
// K4: probs = softmax(logits) written in place to attn; out_sel += P @ V
// grid (BH, 4 jsplits of 512 keys), block 256. 8 inner tiles of 64 keys.
// ============================================================================
__global__ void k_pv(const float* __restrict__ v, float* __restrict__ attn) {
    __shared__ float vs[64 * DQ];     // 16 KB
    __shared__ float ps[NSEL * 64];   // 10 KB
    __shared__ float sMax[NSEL], sInv[NSEL];

    int bh = blockIdx.x, js = blockIdx.y, t = threadIdx.x;
    if (t < NSEL) { sMax[t] = g_rowMax[bh * NSEL + t]; sInv[t] = g_rowInv[bh * NSEL + t]; }

    float* attnBH = attn + (size_t)bh * NSEL * LQ;
    const float* vBH = v + (size_t)bh * LQ * DQ;

    int tx = t & 31, ty = t >> 5;
    int g = ty >> 2;       // jj half
    int sy = ty & 3;       // row group

    float acc[10][2];
#pragma unroll
    for (int r = 0; r < 10; r++) { acc[r][0] = 0.0f; acc[r][1] = 0.0f; }
    __syncthreads();

    for (int tile = 0; tile < 8; tile++) {
        int j0 = js * 512 + tile * 64;
        __syncthreads();
        const float4* vsrc = reinterpret_cast<const float4*>(vBH + (size_t)j0 * DQ);
        float4* vdst = reinterpret_cast<float4*>(vs);
        for (int e = t; e < 64 * DQ / 4; e += 256) vdst[e] = vsrc[e];
        for (int e = t; e < NSEL * 64; e += 256) {
            int s = e >> 6, jj = e & 63;
            size_t a = (size_t)s * LQ + j0 + jj;
            float l = attnBH[a];
            float p = expf(l - sMax[s]) * sInv[s];
            attnBH[a] = p;
            ps[e] = p;
        }
        __syncthreads();
#pragma unroll 4
        for (int jl = g * 32; jl < g * 32 + 32; jl++) {
            float2 vv = *reinterpret_cast<const float2*>(&vs[jl * DQ + 2 * tx]);
#pragma unroll
            for (int r = 0; r < 10; r++) {
                float p = ps[(sy + 4 * r) * 64 + jl];
                acc[r][0] = fmaf(p, vv.x, acc[r][0]);
                acc[r][1] = fmaf(p, vv.y, acc[r][1]);
            }
        }
    }
#pragma unroll
    for (int r = 0; r < 10; r++) {
        int s = sy + 4 * r;
        atomicAdd(&g_outSel[(bh * NSEL + s) * DQ + 2 * tx], acc[r][0]);
        atomicAdd(&g_outSel[(bh * NSEL + s) * DQ + 2 * tx + 1], acc[r][1]);
    }
}

// ============================================================================
// K6: scatter out_sel rows into out at the selected positions
// ============================================================================
__global__ void k_scatter(float* __restrict__ out) {   // grid BH, 256 thr
    int bh = blockIdx.x, t = threadIdx.x;
    for (int e = t; e < NSEL * DQ; e += 256) {
        int s = e >> 6, d = e & 63;
        out[((size_t)bh * LQ + g_topidx[bh * NSEL + s]) * DQ + d] =
            g_outSel[bh * NSEL * DQ + e];
    }
}

// ============================================================================
extern "C" void kernel_launch(void* const* d_in, const int* in_sizes, int n_in,
                              void* d_out, int out_size) {
    const float* q = (const float*)d_in[0];
    const float* k = (const float*)d_in[1];
    const float* v = (const float*)d_in[2];
    const int* ridx = (const int*)d_in[3];

    float* out  = (float*)d_out;                        // [BH, L, D]
    float* attn = out + (size_t)BH * LQ * DQ;           // [BH, NSEL, L]

    // 1. measure (chunked smem gather)
    cudaFuncSetAttribute(k_measure, cudaFuncAttributeMaxDynamicSharedMemorySize, SMEM_MEAS);
    k_measure<<<BH * 8, 512, SMEM_MEAS>>>(q, k, ridx);
    // 2. top-k selection (radix select)
    k_topk<<<BH, 256>>>();
    // 3. logits + partial softmax stats
    {
        dim3 grid(BH, 8);
        k_logits<<<grid, 256>>>(q, k, attn);
    }
    // 3b. combine stats, zero out_sel
    k_combine<<<BH, 64>>>();
    // 5. cumsum(v) -> out
    {
        dim3 grid(BH, 16);
        k_csumA<<<grid, 256>>>(v);
        k_csumB<<<BH, 64>>>();
        k_csumC<<<grid, 64>>>(v, out);
    }
    // 4. softmax probs (in place) + P@V partial accumulation
    {
        dim3 grid(BH, 4);
        k_pv<<<grid, 256>>>(v, attn);
    }
    // 6. scatter selected rows into out
    k_scatter<<<BH, 256>>>(out);
}